// round 2
// baseline (speedup 1.0000x reference)
#include <cuda_runtime.h>
#include <cstddef>

// Problem constants
#define B  32
#define S  128
#define NI 64
#define H  1024
#define T  4

#define DECAY     0.9f
#define THRESHOLD 1.0f
#define BETA      5.0f

#define HCHUNK  128     // h values per block
#define THREADS 128     // one thread per h

__global__ void __launch_bounds__(THREADS)
lif_fused_kernel(const float* __restrict__ x,
                 const float* __restrict__ enc,
                 float* __restrict__ out)
{
    __shared__ float enc_sh[NI * HCHUNK];

    const int b   = blockIdx.x >> 3;        // / (H/HCHUNK)
    const int hc  = blockIdx.x & 7;
    const int h0  = hc * HCHUNK;
    const int tid = threadIdx.x;
    const int h   = h0 + tid;

    // Stage encoding chunk in shared (conflict-free: stride HCHUNK rows)
    #pragma unroll
    for (int i = 0; i < NI; ++i)
        enc_sh[i * HCHUNK + tid] = enc[i * H + h];
    __syncthreads();

    const float* __restrict__ xb  = x   + (size_t)b * S * NI * H + h;
    float* __restrict__       ob  = out + (size_t)b * (S * T) * H + h;

    float v = 0.0f;

    for (int s = 0; s < S; ++s) {
        const float* __restrict__ xs = xb + (size_t)s * NI * H;

        // drive[b,s,h] = sum_i x[b,s,i,h] * enc[i,h]
        float acc0 = 0.f, acc1 = 0.f, acc2 = 0.f, acc3 = 0.f;
        #pragma unroll
        for (int i = 0; i < NI; i += 4) {
            acc0 = fmaf(xs[(size_t)(i + 0) * H], enc_sh[(i + 0) * HCHUNK + tid], acc0);
            acc1 = fmaf(xs[(size_t)(i + 1) * H], enc_sh[(i + 1) * HCHUNK + tid], acc1);
            acc2 = fmaf(xs[(size_t)(i + 2) * H], enc_sh[(i + 2) * HCHUNK + tid], acc2);
            acc3 = fmaf(xs[(size_t)(i + 3) * H], enc_sh[(i + 3) * HCHUNK + tid], acc3);
        }
        const float drive = (acc0 + acc1) + (acc2 + acc3);

        // NUM_TIME_STEPS LIF integrations with the same drive
        float* __restrict__ o = ob + (size_t)(s * T) * H;
        #pragma unroll
        for (int t = 0; t < T; ++t) {
            v = fmaf(DECAY, v, drive);
            const float z     = BETA * (v - THRESHOLD);
            const float spike = __fdividef(1.0f, 1.0f + __expf(-z));
            v -= spike * THRESHOLD;
            o[(size_t)t * H] = spike;
        }
    }

    // v_final appended after output_sequence
    out[(size_t)B * S * T * H + (size_t)b * H + h] = v;
}

extern "C" void kernel_launch(void* const* d_in, const int* in_sizes, int n_in,
                              void* d_out, int out_size)
{
    const float* x   = (const float*)d_in[0];   // [B,S,I,H] fp32
    const float* enc = (const float*)d_in[1];   // [I,H]     fp32
    float*       out = (float*)d_out;           // [B,S*T,H] ++ [B,H]

    dim3 grid(B * (H / HCHUNK));   // 256 blocks
    dim3 block(THREADS);           // 128 threads
    lif_fused_kernel<<<grid, block>>>(x, enc, out);
}

// round 5
// speedup vs baseline: 1.1223x; 1.1223x over previous
#include <cuda_runtime.h>
#include <cstddef>

// Problem constants
#define B  32
#define S  128
#define NI 64
#define H  1024
#define T  4

#define DECAY     0.9f
#define THRESHOLD 1.0f
#define BETA      5.0f

#define HCHUNK   128    // h values per block (drive kernel)
#define SSLICE   8      // s values per block (drive kernel)
#define NSSLICE  (S / SSLICE)   // 16

// Scratch for intermediate drive[B,S,H] (16.8 MB) — static device array,
// allowed under the allocation rules.
__device__ float g_drive[(size_t)B * S * H];

// ---------------------------------------------------------------------------
// Kernel 1: drive[b,s,h] = sum_i x[b,s,i,h] * enc[i,h]
// grid: (NSSLICE, H/HCHUNK, B), block: 128 threads (one per h in chunk)
// ---------------------------------------------------------------------------
__global__ void __launch_bounds__(HCHUNK)
drive_kernel(const float* __restrict__ x,
             const float* __restrict__ enc)
{
    __shared__ float enc_sh[NI * HCHUNK];

    const int ss  = blockIdx.x;          // s-slice index
    const int hc  = blockIdx.y;          // h-chunk index
    const int b   = blockIdx.z;
    const int tid = threadIdx.x;
    const int h   = hc * HCHUNK + tid;

    // Stage encoding chunk in shared (conflict-free)
    #pragma unroll
    for (int i = 0; i < NI; ++i)
        enc_sh[i * HCHUNK + tid] = enc[i * H + h];
    __syncthreads();

    const int s0 = ss * SSLICE;
    const float* __restrict__ xb = x + (size_t)b * S * NI * H + h;
    float* __restrict__ db = g_drive + (size_t)b * S * H + h;

    for (int so = 0; so < SSLICE; ++so) {
        const int s = s0 + so;
        const float* __restrict__ xs = xb + (size_t)s * NI * H;

        float acc0 = 0.f, acc1 = 0.f, acc2 = 0.f, acc3 = 0.f;
        #pragma unroll
        for (int i = 0; i < NI; i += 4) {
            acc0 = fmaf(xs[(size_t)(i + 0) * H], enc_sh[(i + 0) * HCHUNK + tid], acc0);
            acc1 = fmaf(xs[(size_t)(i + 1) * H], enc_sh[(i + 1) * HCHUNK + tid], acc1);
            acc2 = fmaf(xs[(size_t)(i + 2) * H], enc_sh[(i + 2) * HCHUNK + tid], acc2);
            acc3 = fmaf(xs[(size_t)(i + 3) * H], enc_sh[(i + 3) * HCHUNK + tid], acc3);
        }
        db[(size_t)s * H] = (acc0 + acc1) + (acc2 + acc3);
    }
}

// ---------------------------------------------------------------------------
// Kernel 2: LIF scan over S*T steps per (b,h) lane
// grid: 256 blocks x 128 threads (one thread per lane)
// ---------------------------------------------------------------------------
__global__ void __launch_bounds__(128)
lif_scan_kernel(float* __restrict__ out)
{
    const int lane = blockIdx.x * 128 + threadIdx.x;   // 0 .. B*H-1
    const int b = lane >> 10;          // / H
    const int h = lane & (H - 1);

    const float* __restrict__ db = g_drive + (size_t)b * S * H + h;
    float* __restrict__ ob = out + (size_t)b * (S * T) * H + h;

    float v = 0.0f;
    float d_next = db[0];              // prefetch

    for (int s = 0; s < S; ++s) {
        const float drive = d_next;
        if (s + 1 < S) d_next = db[(size_t)(s + 1) * H];

        float* __restrict__ o = ob + (size_t)(s * T) * H;
        #pragma unroll
        for (int t = 0; t < T; ++t) {
            v = fmaf(DECAY, v, drive);
            const float z     = BETA * (v - THRESHOLD);
            const float spike = __fdividef(1.0f, 1.0f + __expf(-z));
            v -= spike * THRESHOLD;
            o[(size_t)t * H] = spike;
        }
    }

    // v_final appended after output_sequence
    out[(size_t)B * S * T * H + lane] = v;
}

extern "C" void kernel_launch(void* const* d_in, const int* in_sizes, int n_in,
                              void* d_out, int out_size)
{
    const float* x   = (const float*)d_in[0];   // [B,S,I,H] fp32
    const float* enc = (const float*)d_in[1];   // [I,H]     fp32
    float*       out = (float*)d_out;           // [B,S*T,H] ++ [B,H]

    dim3 g1(NSSLICE, H / HCHUNK, B);   // 16 x 8 x 32 = 4096 blocks
    drive_kernel<<<g1, HCHUNK>>>(x, enc);

    lif_scan_kernel<<<(B * H) / 128, 128>>>(out);
}